// round 6
// baseline (speedup 1.0000x reference)
#include <cuda_runtime.h>
#include <math.h>

// BackflowNet: B=128, N=64, D=2, H=64, M=64, L=2.
// One CTA per batch, split into TWO independent 128-thread groups.
// Each group owns a tile, an accumulator, and half the i-rows; all i-loop
// synchronization is per-group named barriers (no CTA syncs in the loop).
// GEMM mainloop in packed f32x2 (FFMA2).

#define TPB 256

__device__ float g_he[128u * 64u * 64u * 64u];   // [b][i][j][m]

__device__ __forceinline__ float gelu_exact(float x) {
    return 0.5f * x * (1.0f + erff(x * 0.70710678118654752f));
}
__device__ __forceinline__ unsigned long long pk2(float lo, float hi) {
    unsigned long long r;
    asm("mov.b64 %0, {%1, %2};" : "=l"(r) : "f"(lo), "f"(hi));
    return r;
}
__device__ __forceinline__ void upk2(unsigned long long v, float& lo, float& hi) {
    asm("mov.b64 {%0, %1}, %2;" : "=f"(lo), "=f"(hi) : "l"(v));
}
__device__ __forceinline__ void fma2(unsigned long long& d, unsigned long long a, unsigned long long b) {
    asm("fma.rn.f32x2 %0, %1, %2, %0;" : "+l"(d) : "l"(a), "l"(b));
}
__device__ __forceinline__ void barg(int id) {
    asm volatile("bar.sync %0, 128;" :: "r"(id) : "memory");
}

// SMEM layout (floats)
#define OFF_HV    0
#define OFF_PRE   4096
#define OFF_ACC0  8192
#define OFF_ACC1  12288
#define OFF_T0    16384     // [64][68]
#define OFF_T1    20736
#define OFF_W1    25088
#define OFF_W2    29184
#define OFF_W3    33280
#define OFF_W0    37376
#define OFF_XS    41472
#define OFF_SP    41600
#define OFF_EW1   41664     // [4][64]
#define OFF_SB0   41920
#define OFF_SB1   41984
#define OFF_SB2   42048
#define OFF_SB3   42112
#define OFF_SB4   42176
#define OFF_F4    42240     // [2][64][4]
#define OFF_DX    42752
#define OFF_MN    42880
#define SMEM_FLOATS 42884
#define SMEM_BYTES (SMEM_FLOATS * 4)

#define RANK1(rr, av, wv) \
    rr[0]=fmaf(av, wv.x, rr[0]); rr[1]=fmaf(av, wv.y, rr[1]); \
    rr[2]=fmaf(av, wv.z, rr[2]); rr[3]=fmaf(av, wv.w, rr[3]);
#define TILE4(R, a0v, a1v, a2v, a3v, W) \
    RANK1(R[0], a0v, W) RANK1(R[1], a1v, W) RANK1(R[2], a2v, W) RANK1(R[3], a3v, W)

// ---- CTA-wide scalar 64x64x64 GEMM (small stages) ----
__device__ __forceinline__ void mm64(
    const float* __restrict__ in, int istride,
    const float* __restrict__ w,
    const float* __restrict__ bias,
    float* __restrict__ out, int ostride,
    int act, float inscale, bool accum, int tid)
{
    const int mb = (tid & 15) * 4;
    const int jb = (tid >> 4) * 4;
    const float* i0 = in + jb * istride;
    const float* i1 = i0 + istride;
    const float* i2 = i1 + istride;
    const float* i3 = i2 + istride;
    float r[4][4] = {};
    #pragma unroll 4
    for (int k = 0; k < 64; k += 4) {
        float4 w0 = *(const float4*)(w + (k + 0) * 64 + mb);
        float4 w1 = *(const float4*)(w + (k + 1) * 64 + mb);
        float4 w2 = *(const float4*)(w + (k + 2) * 64 + mb);
        float4 w3 = *(const float4*)(w + (k + 3) * 64 + mb);
        float4 a0 = *(const float4*)(i0 + k);
        float4 a1 = *(const float4*)(i1 + k);
        float4 a2 = *(const float4*)(i2 + k);
        float4 a3 = *(const float4*)(i3 + k);
        TILE4(r, a0.x, a1.x, a2.x, a3.x, w0)
        TILE4(r, a0.y, a1.y, a2.y, a3.y, w1)
        TILE4(r, a0.z, a1.z, a2.z, a3.z, w2)
        TILE4(r, a0.w, a1.w, a2.w, a3.w, w3)
    }
    #pragma unroll
    for (int u = 0; u < 4; u++) {
        float badd = bias ? bias[mb + u] : 0.f;
        #pragma unroll
        for (int v = 0; v < 4; v++) {
            float val = fmaf(r[v][u], inscale, badd);
            if (act == 1) val = gelu_exact(val);
            else if (act == 2) val = tanhf(val);
            float* o = out + (jb + v) * ostride + mb + u;
            if (accum) *o += val; else *o = val;
        }
    }
}

// ---- group (128-thread) f32x2 GEMM on one 64x64 tile; in-place safe via
// group-local named barriers. accp mode: masked accumulate, no tile write.
__device__ __forceinline__ void mmx2g(
    const float* __restrict__ in, int istride,
    const float* __restrict__ w,
    const float* __restrict__ bias,
    const float* __restrict__ addrow,
    float* __restrict__ outT,            // stride 68 (ignored in acc mode)
    float* __restrict__ gmir,            // optional global mirror, stride 64
    float* __restrict__ accp, int maskrow,
    int act, int t128, int barid)
{
    const int mb = (t128 & 7) * 8;
    const int jb = (t128 >> 3) * 4;
    unsigned long long A[4][4];
    #pragma unroll
    for (int r = 0; r < 4; r++)
        #pragma unroll
        for (int p = 0; p < 4; p++) A[r][p] = 0ull;

    const float* base = in + jb * istride;
    #pragma unroll 4
    for (int k = 0; k < 64; k += 4) {
        float4 av0 = *(const float4*)(base + 0 * istride + k);
        float4 av1 = *(const float4*)(base + 1 * istride + k);
        float4 av2 = *(const float4*)(base + 2 * istride + k);
        float4 av3 = *(const float4*)(base + 3 * istride + k);
        #pragma unroll
        for (int kk = 0; kk < 4; kk++) {
            ulonglong2 wlo = *(const ulonglong2*)(w + (k + kk) * 64 + mb);
            ulonglong2 whi = *(const ulonglong2*)(w + (k + kk) * 64 + mb + 4);
            float a0 = (kk == 0) ? av0.x : (kk == 1) ? av0.y : (kk == 2) ? av0.z : av0.w;
            float a1 = (kk == 0) ? av1.x : (kk == 1) ? av1.y : (kk == 2) ? av1.z : av1.w;
            float a2 = (kk == 0) ? av2.x : (kk == 1) ? av2.y : (kk == 2) ? av2.z : av2.w;
            float a3 = (kk == 0) ? av3.x : (kk == 1) ? av3.y : (kk == 2) ? av3.z : av3.w;
            unsigned long long ab;
            ab = pk2(a0, a0);
            fma2(A[0][0], ab, wlo.x); fma2(A[0][1], ab, wlo.y);
            fma2(A[0][2], ab, whi.x); fma2(A[0][3], ab, whi.y);
            ab = pk2(a1, a1);
            fma2(A[1][0], ab, wlo.x); fma2(A[1][1], ab, wlo.y);
            fma2(A[1][2], ab, whi.x); fma2(A[1][3], ab, whi.y);
            ab = pk2(a2, a2);
            fma2(A[2][0], ab, wlo.x); fma2(A[2][1], ab, wlo.y);
            fma2(A[2][2], ab, whi.x); fma2(A[2][3], ab, whi.y);
            ab = pk2(a3, a3);
            fma2(A[3][0], ab, wlo.x); fma2(A[3][1], ab, wlo.y);
            fma2(A[3][2], ab, whi.x); fma2(A[3][3], ab, whi.y);
        }
    }
    float badd[8];
    #pragma unroll
    for (int u = 0; u < 8; u++)
        badd[u] = (bias ? bias[mb + u] : 0.f) + (addrow ? addrow[mb + u] : 0.f);
    float o[4][8];
    #pragma unroll
    for (int r = 0; r < 4; r++)
        #pragma unroll
        for (int p = 0; p < 4; p++) {
            float lo, hi;
            upk2(A[r][p], lo, hi);
            float v0 = lo + badd[2 * p];
            float v1 = hi + badd[2 * p + 1];
            if (act) { v0 = gelu_exact(v0); v1 = gelu_exact(v1); }
            o[r][2 * p] = v0; o[r][2 * p + 1] = v1;
        }

    if (accp) {
        // thread-exclusive (j,m) region: race-free accumulate, skip masked row
        #pragma unroll
        for (int r = 0; r < 4; r++) {
            int j = jb + r;
            if (j != maskrow) {
                float* a = accp + j * 64 + mb;
                #pragma unroll
                for (int u = 0; u < 8; u++) a[u] += o[r][u];
            }
        }
        barg(barid);        // release the input tile for the next writer
    } else {
        barg(barid);        // all reads of 'in' done before in-place writes
        #pragma unroll
        for (int r = 0; r < 4; r++) {
            float4 lo4 = make_float4(o[r][0], o[r][1], o[r][2], o[r][3]);
            float4 hi4 = make_float4(o[r][4], o[r][5], o[r][6], o[r][7]);
            *(float4*)(outT + (jb + r) * 68 + mb)     = lo4;
            *(float4*)(outT + (jb + r) * 68 + mb + 4) = hi4;
            if (gmir) {
                *(float4*)(gmir + (jb + r) * 64 + mb)     = lo4;
                *(float4*)(gmir + (jb + r) * 64 + mb + 4) = hi4;
            }
        }
        barg(barid);        // writes visible before next stage reads
    }
}

__global__ void __launch_bounds__(TPB, 1)
bf_kernel(const float* __restrict__ x, const float* __restrict__ spin,
          const float* __restrict__ node_w1, const float* __restrict__ node_b1,
          const float* __restrict__ node_w2, const float* __restrict__ node_b2,
          const float* __restrict__ edge_w1, const float* __restrict__ edge_b1,
          const float* __restrict__ edge_w2, const float* __restrict__ edge_b2,
          const float* __restrict__ v2e_w1, const float* __restrict__ v2e_b1,
          const float* __restrict__ v2e_w2, const float* __restrict__ v2e_b2,
          const float* __restrict__ e2v_w1, const float* __restrict__ e2v_b1,
          const float* __restrict__ e2v_w2, const float* __restrict__ e2v_b2,
          const float* __restrict__ head_w1, const float* __restrict__ head_b1,
          const float* __restrict__ head_w2, const float* __restrict__ head_b2,
          const float* __restrict__ scale, float* __restrict__ out)
{
    const int b = blockIdx.x;
    const int tid = threadIdx.x;
    extern __shared__ float sm[];
    float* s_hv  = sm + OFF_HV;
    float* s_pre = sm + OFF_PRE;
    float* sW1   = sm + OFF_W1;
    float* sW2   = sm + OFF_W2;
    float* sW3   = sm + OFF_W3;
    float* sW0   = sm + OFF_W0;
    float* s_xs  = sm + OFF_XS;
    float* s_sp  = sm + OFF_SP;
    float* sEW1  = sm + OFF_EW1;
    float* sb0   = sm + OFF_SB0;
    float* sb1   = sm + OFF_SB1;
    float* sb2   = sm + OFF_SB2;
    float* sb3   = sm + OFF_SB3;
    float* sb4   = sm + OFF_SB4;
    float* s_dx  = sm + OFF_DX;
    float* s_mn  = sm + OFF_MN;

    float* ghe_b = g_he + ((size_t)b << 18);
    const int g     = tid >> 7;          // group 0/1
    const int t128  = tid & 127;
    const int barid = 1 + g;
    float* T    = sm + OFF_T0 + g * 4352;
    float* accg = sm + OFF_ACC0 + g * 4096;
    float* f4g  = sm + OFF_F4 + g * 256;
    float* T0   = sm + OFF_T0;

    // ---- stage inputs + node weights ----
    if (tid < 128) s_xs[tid] = x[b * 128 + tid];
    if (tid < 64)  s_sp[tid] = spin[b * 64 + tid];
    for (int t = tid; t < 4096; t += TPB) sW0[t] = node_w2[t];
    if (tid < 192) sEW1[tid] = node_w1[tid];
    if (tid < 64) { sb0[tid] = node_b1[tid]; sb1[tid] = node_b2[tid]; }
    __syncthreads();

    for (int t = tid; t < 4096; t += TPB) {
        int i = t >> 6, h = t & 63;
        float v = fmaf(s_xs[i * 2], sEW1[h],
                  fmaf(s_xs[i * 2 + 1], sEW1[64 + h],
                  fmaf(s_sp[i], sEW1[128 + h], sb0[h])));
        T0[i * 68 + h] = gelu_exact(v);
    }
    __syncthreads();
    mm64(T0, 68, sW0, sb1, s_hv, 64, 0, 1.f, false, tid);
    __syncthreads();

    const float inv = 1.0f / 63.0f;
    for (int l = 0; l < 2; l++) {
        // ---- CTA-wide layer prologue ----
        for (int t = tid; t < 4096; t += TPB) {
            sW0[t] = v2e_w1[l * 8192 + t];
            sm[OFF_ACC0 + t] = 0.f;
            sm[OFF_ACC1 + t] = 0.f;
        }
        if (tid < 64) sb0[tid] = v2e_b1[l * 64 + tid];
        __syncthreads();
        mm64(s_hv, 64, sW0, sb0, s_pre, 64, 0, 1.f, false, tid);
        __syncthreads();
        for (int t = tid; t < 4096; t += TPB) {
            sW1[t] = v2e_w1[l * 8192 + 4096 + t];
            sW2[t] = v2e_w2[l * 4096 + t];
            sW3[t] = e2v_w1[l * 4096 + t];
        }
        if (l == 0) {
            for (int t = tid; t < 4096; t += TPB) sW0[t] = edge_w2[t];
            if (tid < 256) sEW1[tid] = edge_w1[tid];
            if (tid < 64) { sb1[tid] = edge_b1[tid]; sb2[tid] = edge_b2[tid]; }
        }
        if (tid < 64) { sb3[tid] = v2e_b2[l * 64 + tid]; sb4[tid] = e2v_b1[l * 64 + tid]; }
        __syncthreads();

        // ---- i-loop: groups fully decoupled ----
        for (int iq = 0; iq < 32; iq++) {
            const int ig = 2 * iq + g;
            float* ghe_row = ghe_b + ((size_t)ig << 12);
            if (l == 0) {
                if (t128 < 64) {
                    int j = t128;
                    float d0 = s_xs[j * 2] - s_xs[ig * 2];
                    float d1 = s_xs[j * 2 + 1] - s_xs[ig * 2 + 1];
                    float r2 = d0 * d0 + d1 * d1;
                    float rr = sqrtf(r2 + 1e-12f);
                    float* f = f4g + j * 4;
                    f[0] = d0; f[1] = d1; f[2] = rr; f[3] = r2;
                }
                barg(barid);
                for (int t = t128; t < 4096; t += 128) {
                    int j = t >> 6, m = t & 63;
                    const float* f = f4g + j * 4;
                    float v = fmaf(f[0], sEW1[m],
                              fmaf(f[1], sEW1[64 + m],
                              fmaf(f[2], sEW1[128 + m],
                              fmaf(f[3], sEW1[192 + m], sb1[m]))));
                    T[j * 68 + m] = gelu_exact(v);
                }
                barg(barid);
                mmx2g(T, 68, sW0, sb2, 0, T, 0, 0, -1, 0, t128, barid);               // he0
                mmx2g(T, 68, sW1, 0, s_pre + ig * 64, T, 0, 0, -1, 1, t128, barid);   // v2e hidden
            } else {
                mmx2g(ghe_row, 64, sW1, 0, s_pre + ig * 64, T, 0, 0, -1, 1, t128, barid);
            }
            mmx2g(T, 68, sW2, sb3, 0, T, (l == 0) ? ghe_row : 0, 0, -1, 0, t128, barid); // he'
            mmx2g(T, 68, sW3, sb4, 0, 0, 0, accg, ig, 1, t128, barid);                   // masked acc
        }
        __syncthreads();

        // ---- reduce the two group accumulators, then hoisted e2v W2 GEMM ----
        for (int t = tid; t < 4096; t += TPB) sm[OFF_ACC0 + t] += sm[OFF_ACC1 + t];
        for (int t = tid; t < 4096; t += TPB) sW0[t] = e2v_w2[l * 4096 + t];
        if (tid < 64) sb0[tid] = e2v_b2[l * 64 + tid];
        __syncthreads();
        mm64(sm + OFF_ACC0, 64, sW0, sb0, s_hv, 64, 0, inv, true, tid);
        __syncthreads();
    }

    // ---- head ----
    for (int t = tid; t < 4096; t += TPB) sW0[t] = head_w1[t];
    if (tid < 64) sb0[tid] = head_b1[tid];
    __syncthreads();
    mm64(s_hv, 64, sW0, sb0, T0, 68, 2, 1.f, false, tid);
    __syncthreads();
    if (tid < 128) {
        int j = tid >> 1, d = tid & 1;
        float sp = log1pf(expf(scale[0]));
        float s = head_b2[d];
        const float* a = T0 + j * 68;
        #pragma unroll
        for (int k = 0; k < 64; k++) s = fmaf(a[k], head_w2[k * 2 + d], s);
        s_dx[tid] = s * sp;
    }
    __syncthreads();
    if (tid < 2) {
        float s = 0.f;
        #pragma unroll
        for (int j = 0; j < 64; j++) s += s_dx[j * 2 + tid];
        s_mn[tid] = s * (1.0f / 64.0f);
    }
    __syncthreads();
    if (tid < 128) out[b * 128 + tid] = s_dx[tid] - s_mn[tid & 1];
}

extern "C" void kernel_launch(void* const* d_in, const int* in_sizes, int n_in,
                              void* d_out, int out_size) {
    (void)out_size;
    const float* ptr[23];
    bool dict_order = (n_in >= 23 && in_sizes[0] == 16384 && in_sizes[2] == 192);
    if (dict_order) {
        for (int i = 0; i < 23; i++) ptr[i] = (const float*)d_in[i];
    } else {
        static const int alpha_to_dict[23] = {
            15, 17, 14, 16,  7,  9,  6,  8, 19, 21, 18, 20,
             3,  5,  2,  4, 22,  1, 11, 13, 10, 12,  0
        };
        for (int i = 0; i < 23; i++) ptr[alpha_to_dict[i]] = (const float*)d_in[i];
    }
    float* out = (float*)d_out;

    cudaFuncSetAttribute(bf_kernel, cudaFuncAttributeMaxDynamicSharedMemorySize, SMEM_BYTES);
    bf_kernel<<<128, TPB, SMEM_BYTES>>>(
        ptr[0], ptr[1], ptr[2], ptr[3], ptr[4], ptr[5],
        ptr[6], ptr[7], ptr[8], ptr[9],
        ptr[10], ptr[11], ptr[12], ptr[13],
        ptr[14], ptr[15], ptr[16], ptr[17],
        ptr[18], ptr[19], ptr[20], ptr[21], ptr[22], out);
}

// round 7
// speedup vs baseline: 1.3078x; 1.3078x over previous
#include <cuda_runtime.h>
#include <math.h>

// BackflowNet: B=128, N=64, D=2, H=64, M=64, L=2.
// One CTA per batch. 4 tiles x 64 threads (8x8 f32x2 register tiles — the
// R5 geometry), organized as 2 independent 128-thread groups (2 tiles each)
// synchronized only by group-local named barriers inside the i-loop.

#define TPB 256

__device__ float g_he[128u * 64u * 64u * 64u];   // [b][i][j][m]

__device__ __forceinline__ float gelu_exact(float x) {
    return 0.5f * x * (1.0f + erff(x * 0.70710678118654752f));
}
__device__ __forceinline__ unsigned long long pk2(float lo, float hi) {
    unsigned long long r;
    asm("mov.b64 %0, {%1, %2};" : "=l"(r) : "f"(lo), "f"(hi));
    return r;
}
__device__ __forceinline__ void upk2(unsigned long long v, float& lo, float& hi) {
    asm("mov.b64 {%0, %1}, %2;" : "=f"(lo), "=f"(hi) : "l"(v));
}
__device__ __forceinline__ void fma2(unsigned long long& d, unsigned long long a, unsigned long long b) {
    asm("fma.rn.f32x2 %0, %1, %2, %0;" : "+l"(d) : "l"(a), "l"(b));
}
__device__ __forceinline__ void barg(int id) {
    asm volatile("bar.sync %0, 128;" :: "r"(id) : "memory");
}

// SMEM layout (floats)
#define OFF_HV    0
#define OFF_PRE   4096
#define OFF_ACC0  8192
#define OFF_ACC1  12288
#define OFF_T0    16384     // 4 tiles [64][68]
#define T_STRIDE  4352
#define OFF_W1    33792
#define OFF_W2    37888
#define OFF_W3    41984
#define OFF_W0    46080
#define OFF_XS    50176
#define OFF_SP    50304
#define OFF_EW1   50368     // [4][64]
#define OFF_SB0   50624
#define OFF_SB1   50688
#define OFF_SB2   50752
#define OFF_SB3   50816
#define OFF_SB4   50880
#define OFF_F4    50944     // [4][64][4]
#define OFF_DX    51968
#define OFF_MN    52096
#define SMEM_FLOATS 52100
#define SMEM_BYTES (SMEM_FLOATS * 4)

#define RANK1(rr, av, wv) \
    rr[0]=fmaf(av, wv.x, rr[0]); rr[1]=fmaf(av, wv.y, rr[1]); \
    rr[2]=fmaf(av, wv.z, rr[2]); rr[3]=fmaf(av, wv.w, rr[3]);
#define TILE4(R, a0v, a1v, a2v, a3v, W) \
    RANK1(R[0], a0v, W) RANK1(R[1], a1v, W) RANK1(R[2], a2v, W) RANK1(R[3], a3v, W)

// ---- CTA-wide scalar 64x64x64 GEMM (small stages) ----
__device__ __forceinline__ void mm64(
    const float* __restrict__ in, int istride,
    const float* __restrict__ w,
    const float* __restrict__ bias,
    float* __restrict__ out, int ostride,
    int act, float inscale, bool accum, int tid)
{
    const int mb = (tid & 15) * 4;
    const int jb = (tid >> 4) * 4;
    const float* i0 = in + jb * istride;
    const float* i1 = i0 + istride;
    const float* i2 = i1 + istride;
    const float* i3 = i2 + istride;
    float r[4][4] = {};
    #pragma unroll 4
    for (int k = 0; k < 64; k += 4) {
        float4 w0 = *(const float4*)(w + (k + 0) * 64 + mb);
        float4 w1 = *(const float4*)(w + (k + 1) * 64 + mb);
        float4 w2 = *(const float4*)(w + (k + 2) * 64 + mb);
        float4 w3 = *(const float4*)(w + (k + 3) * 64 + mb);
        float4 a0 = *(const float4*)(i0 + k);
        float4 a1 = *(const float4*)(i1 + k);
        float4 a2 = *(const float4*)(i2 + k);
        float4 a3 = *(const float4*)(i3 + k);
        TILE4(r, a0.x, a1.x, a2.x, a3.x, w0)
        TILE4(r, a0.y, a1.y, a2.y, a3.y, w1)
        TILE4(r, a0.z, a1.z, a2.z, a3.z, w2)
        TILE4(r, a0.w, a1.w, a2.w, a3.w, w3)
    }
    #pragma unroll
    for (int u = 0; u < 4; u++) {
        float badd = bias ? bias[mb + u] : 0.f;
        #pragma unroll
        for (int v = 0; v < 4; v++) {
            float val = fmaf(r[v][u], inscale, badd);
            if (act == 1) val = gelu_exact(val);
            else if (act == 2) val = tanhf(val);
            float* o = out + (jb + v) * ostride + mb + u;
            if (accum) *o += val; else *o = val;
        }
    }
}

// ---- f32x2 GEMM on one 64x64 tile: 64 threads, 8x8 per thread (R5 geometry).
// In-place safe via the group's named barrier (pre-write + post-write).
// Row maskrow zeroed after activation. Optional global mirror (stride 64).
__device__ __forceinline__ void mmx2g(
    const float* in, int istride,
    const float* __restrict__ w,
    const float* __restrict__ bias,
    const float* __restrict__ addrow,
    float* outT,                      // stride 68
    float* __restrict__ gmir,
    int maskrow, int act, int t64, int barid)
{
    const int mb = (t64 & 7) * 8;
    const int jb = (t64 >> 3) * 8;
    unsigned long long A[8][4];
    #pragma unroll
    for (int r = 0; r < 8; r++)
        #pragma unroll
        for (int p = 0; p < 4; p++) A[r][p] = 0ull;

    const float* base = in + jb * istride;
    #pragma unroll 2
    for (int k = 0; k < 64; k += 4) {
        float4 av[8];
        #pragma unroll
        for (int r = 0; r < 8; r++) av[r] = *(const float4*)(base + r * istride + k);
        #pragma unroll
        for (int kk = 0; kk < 4; kk++) {
            ulonglong2 wlo = *(const ulonglong2*)(w + (k + kk) * 64 + mb);
            ulonglong2 whi = *(const ulonglong2*)(w + (k + kk) * 64 + mb + 4);
            #pragma unroll
            for (int r = 0; r < 8; r++) {
                float a = (kk == 0) ? av[r].x : (kk == 1) ? av[r].y
                        : (kk == 2) ? av[r].z : av[r].w;
                unsigned long long ab = pk2(a, a);
                fma2(A[r][0], ab, wlo.x);
                fma2(A[r][1], ab, wlo.y);
                fma2(A[r][2], ab, whi.x);
                fma2(A[r][3], ab, whi.y);
            }
        }
    }
    float badd[8];
    #pragma unroll
    for (int u = 0; u < 8; u++)
        badd[u] = (bias ? bias[mb + u] : 0.f) + (addrow ? addrow[mb + u] : 0.f);
    float o[8][8];
    #pragma unroll
    for (int r = 0; r < 8; r++) {
        #pragma unroll
        for (int p = 0; p < 4; p++) {
            float lo, hi;
            upk2(A[r][p], lo, hi);
            float v0 = lo + badd[2 * p];
            float v1 = hi + badd[2 * p + 1];
            if (act) { v0 = gelu_exact(v0); v1 = gelu_exact(v1); }
            o[r][2 * p] = v0; o[r][2 * p + 1] = v1;
        }
        if (jb + r == maskrow) {
            #pragma unroll
            for (int u = 0; u < 8; u++) o[r][u] = 0.f;
        }
    }
    barg(barid);     // all reads of 'in' complete before in-place writes
    #pragma unroll
    for (int r = 0; r < 8; r++) {
        float4 lo4 = make_float4(o[r][0], o[r][1], o[r][2], o[r][3]);
        float4 hi4 = make_float4(o[r][4], o[r][5], o[r][6], o[r][7]);
        *(float4*)(outT + (jb + r) * 68 + mb)     = lo4;
        *(float4*)(outT + (jb + r) * 68 + mb + 4) = hi4;
        if (gmir) {
            *(float4*)(gmir + (jb + r) * 64 + mb)     = lo4;
            *(float4*)(gmir + (jb + r) * 64 + mb + 4) = hi4;
        }
    }
    barg(barid);     // writes visible before next stage reads
}

__global__ void __launch_bounds__(TPB, 1)
bf_kernel(const float* __restrict__ x, const float* __restrict__ spin,
          const float* __restrict__ node_w1, const float* __restrict__ node_b1,
          const float* __restrict__ node_w2, const float* __restrict__ node_b2,
          const float* __restrict__ edge_w1, const float* __restrict__ edge_b1,
          const float* __restrict__ edge_w2, const float* __restrict__ edge_b2,
          const float* __restrict__ v2e_w1, const float* __restrict__ v2e_b1,
          const float* __restrict__ v2e_w2, const float* __restrict__ v2e_b2,
          const float* __restrict__ e2v_w1, const float* __restrict__ e2v_b1,
          const float* __restrict__ e2v_w2, const float* __restrict__ e2v_b2,
          const float* __restrict__ head_w1, const float* __restrict__ head_b1,
          const float* __restrict__ head_w2, const float* __restrict__ head_b2,
          const float* __restrict__ scale, float* __restrict__ out)
{
    const int b = blockIdx.x;
    const int tid = threadIdx.x;
    extern __shared__ float sm[];
    float* s_hv  = sm + OFF_HV;
    float* s_pre = sm + OFF_PRE;
    float* sW1   = sm + OFF_W1;
    float* sW2   = sm + OFF_W2;
    float* sW3   = sm + OFF_W3;
    float* sW0   = sm + OFF_W0;
    float* s_xs  = sm + OFF_XS;
    float* s_sp  = sm + OFF_SP;
    float* sEW1  = sm + OFF_EW1;
    float* sb0   = sm + OFF_SB0;
    float* sb1   = sm + OFF_SB1;
    float* sb2   = sm + OFF_SB2;
    float* sb3   = sm + OFF_SB3;
    float* sb4   = sm + OFF_SB4;
    float* s_dx  = sm + OFF_DX;
    float* s_mn  = sm + OFF_MN;

    float* ghe_b = g_he + ((size_t)b << 18);
    const int g     = tid >> 7;           // group 0/1
    const int t128  = tid & 127;
    const int h     = t128 >> 6;          // tile-in-group 0/1
    const int t64   = tid & 63;
    const int barid = 1 + g;
    const int tix   = 2 * g + h;          // global tile index 0..3
    float* T    = sm + OFF_T0 + tix * T_STRIDE;
    float* Tg0  = sm + OFF_T0 + (2 * g) * T_STRIDE;
    float* Tg1  = Tg0 + T_STRIDE;
    float* accg = sm + OFF_ACC0 + g * 4096;
    float* f4t  = sm + OFF_F4 + tix * 256;
    float* T0   = sm + OFF_T0;

    // ---- stage inputs + node weights ----
    if (tid < 128) s_xs[tid] = x[b * 128 + tid];
    if (tid < 64)  s_sp[tid] = spin[b * 64 + tid];
    for (int t = tid; t < 4096; t += TPB) sW0[t] = node_w2[t];
    if (tid < 192) sEW1[tid] = node_w1[tid];
    if (tid < 64) { sb0[tid] = node_b1[tid]; sb1[tid] = node_b2[tid]; }
    __syncthreads();

    for (int t = tid; t < 4096; t += TPB) {
        int i = t >> 6, hh = t & 63;
        float v = fmaf(s_xs[i * 2], sEW1[hh],
                  fmaf(s_xs[i * 2 + 1], sEW1[64 + hh],
                  fmaf(s_sp[i], sEW1[128 + hh], sb0[hh])));
        T0[i * 68 + hh] = gelu_exact(v);
    }
    __syncthreads();
    mm64(T0, 68, sW0, sb1, s_hv, 64, 0, 1.f, false, tid);
    __syncthreads();

    const float inv = 1.0f / 63.0f;
    for (int l = 0; l < 2; l++) {
        // ---- CTA-wide layer prologue ----
        for (int t = tid; t < 4096; t += TPB) {
            sW0[t] = v2e_w1[l * 8192 + t];
            sm[OFF_ACC0 + t] = 0.f;
            sm[OFF_ACC1 + t] = 0.f;
        }
        if (tid < 64) sb0[tid] = v2e_b1[l * 64 + tid];
        __syncthreads();
        mm64(s_hv, 64, sW0, sb0, s_pre, 64, 0, 1.f, false, tid);
        __syncthreads();
        for (int t = tid; t < 4096; t += TPB) {
            sW1[t] = v2e_w1[l * 8192 + 4096 + t];
            sW2[t] = v2e_w2[l * 4096 + t];
            sW3[t] = e2v_w1[l * 4096 + t];
        }
        if (l == 0) {
            for (int t = tid; t < 4096; t += TPB) sW0[t] = edge_w2[t];
            if (tid < 256) sEW1[tid] = edge_w1[tid];
            if (tid < 64) { sb1[tid] = edge_b1[tid]; sb2[tid] = edge_b2[tid]; }
        }
        if (tid < 64) { sb3[tid] = v2e_b2[l * 64 + tid]; sb4[tid] = e2v_b1[l * 64 + tid]; }
        __syncthreads();

        // ---- i-loop: the two groups are fully decoupled ----
        for (int iq = 0; iq < 16; iq++) {
            const int ig = 4 * iq + 2 * g + h;      // this tile's source row
            float* ghe_row = ghe_b + ((size_t)ig << 12);
            if (l == 0) {
                {   // geometry: one j per thread per tile
                    int j = t64;
                    float d0 = s_xs[j * 2] - s_xs[ig * 2];
                    float d1 = s_xs[j * 2 + 1] - s_xs[ig * 2 + 1];
                    float r2 = d0 * d0 + d1 * d1;
                    float rr = sqrtf(r2 + 1e-12f);
                    float* f = f4t + j * 4;
                    f[0] = d0; f[1] = d1; f[2] = rr; f[3] = r2;
                }
                barg(barid);
                {   // edge MLP hidden: thread owns column m=t64 of its tile
                    int m = t64;
                    float w0 = sEW1[m], w1 = sEW1[64 + m], w2 = sEW1[128 + m], w3 = sEW1[192 + m];
                    float bb = sb1[m];
                    #pragma unroll 4
                    for (int j = 0; j < 64; j++) {
                        const float* f = f4t + j * 4;
                        float v = fmaf(f[0], w0, fmaf(f[1], w1, fmaf(f[2], w2, fmaf(f[3], w3, bb))));
                        T[j * 68 + m] = gelu_exact(v);
                    }
                }
                barg(barid);
                mmx2g(T, 68, sW0, sb2, 0, T, 0, -1, 0, t64, barid);               // he0
                mmx2g(T, 68, sW1, 0, s_pre + ig * 64, T, 0, -1, 1, t64, barid);   // v2e hidden
            } else {
                mmx2g(ghe_row, 64, sW1, 0, s_pre + ig * 64, T, 0, -1, 1, t64, barid);
            }
            mmx2g(T, 68, sW2, sb3, 0, T, (l == 0) ? ghe_row : 0, -1, 0, t64, barid);  // he'
            mmx2g(T, 68, sW3, sb4, 0, T, 0, ig, 1, t64, barid);                       // masked g
            // group-local reduce of both tiles into accg (float4, conflict-free)
            for (int t = t128; t < 1024; t += 128) {
                int j = t >> 4, q = (t & 15) * 4;
                float4 a  = *(float4*)(accg + j * 64 + q);
                float4 v0 = *(const float4*)(Tg0 + j * 68 + q);
                float4 v1 = *(const float4*)(Tg1 + j * 68 + q);
                a.x += v0.x + v1.x;
                a.y += v0.y + v1.y;
                a.z += v0.z + v1.z;
                a.w += v0.w + v1.w;
                *(float4*)(accg + j * 64 + q) = a;
            }
            // no trailing barrier: next stage's pre-write barg orders these
            // reduce-reads before any tile overwrite.
        }
        __syncthreads();

        // ---- combine group accumulators, hoisted e2v W2 GEMM ----
        for (int t = tid; t < 4096; t += TPB) sm[OFF_ACC0 + t] += sm[OFF_ACC1 + t];
        for (int t = tid; t < 4096; t += TPB) sW0[t] = e2v_w2[l * 4096 + t];
        if (tid < 64) sb0[tid] = e2v_b2[l * 64 + tid];
        __syncthreads();
        mm64(sm + OFF_ACC0, 64, sW0, sb0, s_hv, 64, 0, inv, true, tid);
        __syncthreads();
    }

    // ---- head ----
    for (int t = tid; t < 4096; t += TPB) sW0[t] = head_w1[t];
    if (tid < 64) sb0[tid] = head_b1[tid];
    __syncthreads();
    mm64(s_hv, 64, sW0, sb0, T0, 68, 2, 1.f, false, tid);
    __syncthreads();
    if (tid < 128) {
        int j = tid >> 1, d = tid & 1;
        float sp = log1pf(expf(scale[0]));
        float s = head_b2[d];
        const float* a = T0 + j * 68;
        #pragma unroll
        for (int k = 0; k < 64; k++) s = fmaf(a[k], head_w2[k * 2 + d], s);
        s_dx[tid] = s * sp;
    }
    __syncthreads();
    if (tid < 2) {
        float s = 0.f;
        #pragma unroll
        for (int j = 0; j < 64; j++) s += s_dx[j * 2 + tid];
        s_mn[tid] = s * (1.0f / 64.0f);
    }
    __syncthreads();
    if (tid < 128) out[b * 128 + tid] = s_dx[tid] - s_mn[tid & 1];
}

extern "C" void kernel_launch(void* const* d_in, const int* in_sizes, int n_in,
                              void* d_out, int out_size) {
    (void)out_size;
    const float* ptr[23];
    bool dict_order = (n_in >= 23 && in_sizes[0] == 16384 && in_sizes[2] == 192);
    if (dict_order) {
        for (int i = 0; i < 23; i++) ptr[i] = (const float*)d_in[i];
    } else {
        static const int alpha_to_dict[23] = {
            15, 17, 14, 16,  7,  9,  6,  8, 19, 21, 18, 20,
             3,  5,  2,  4, 22,  1, 11, 13, 10, 12,  0
        };
        for (int i = 0; i < 23; i++) ptr[alpha_to_dict[i]] = (const float*)d_in[i];
    }
    float* out = (float*)d_out;

    cudaFuncSetAttribute(bf_kernel, cudaFuncAttributeMaxDynamicSharedMemorySize, SMEM_BYTES);
    bf_kernel<<<128, TPB, SMEM_BYTES>>>(
        ptr[0], ptr[1], ptr[2], ptr[3], ptr[4], ptr[5],
        ptr[6], ptr[7], ptr[8], ptr[9],
        ptr[10], ptr[11], ptr[12], ptr[13],
        ptr[14], ptr[15], ptr[16], ptr[17],
        ptr[18], ptr[19], ptr[20], ptr[21], ptr[22], out);
}